// round 14
// baseline (speedup 1.0000x reference)
#include <cuda_runtime.h>
#include <cuda_fp16.h>
#include <math.h>

// Problem constants (fixed by the reference)
#define N1   100000
#define ND1  50000
#define E1   1600000
#define N2   50000
#define ND2  25000
#define E2   800000
#define BC   64          // B*C = 4*16 values per node
#define NEG_SLOPE 0.01f
#define CAP  96          // per-destination bucket capacity (Poisson(32)+11sigma)

// ---------------- scratch (static device globals; no allocations) -----------
__device__ __half g_Xt [(size_t)N1  * BC];        // fp16 node table, [N,64]
__device__ __half g_h1 [(size_t)ND1 * BC];        // fp16 layer-1 output
__device__ int   g_cnt1[ND1];
__device__ int   g_cnt2[ND2];
__device__ uint2 g_eb1[(size_t)ND1 * CAP];        // (src, w-as-half2) records
__device__ uint2 g_eb2[(size_t)ND2 * CAP];

// ---------------- helpers ----------------------------------------------------

__device__ __forceinline__ unsigned pack_w_half2(float w)
{
    unsigned b = __half_as_ushort(__float2half_rn(w));
    return b | (b << 16);                       // duplicated half2
}

// ---------------- kernels ---------------------------------------------------

// Fused: X[b,n,c] (fp32) -> Xt[n, b*16+c] (fp16)  +  zero degree counters.
__global__ void prep_kernel(const float4* __restrict__ X,
                            uint2* __restrict__ Xt,
                            int*   __restrict__ cnt1,
                            int*   __restrict__ cnt2)
{
    int g = blockIdx.x * blockDim.x + threadIdx.x;   // [0, N1*16)
    if (g < N1 * 16) {
        int n  = g >> 4;
        int b  = (g >> 2) & 3;
        int c4 = g & 3;
        float4 v = X[((size_t)b * N1 + n) * 4 + c4];
        __half2 lo = __floats2half2_rn(v.x, v.y);
        __half2 hi = __floats2half2_rn(v.z, v.w);
        uint2 packed;
        packed.x = *reinterpret_cast<unsigned*>(&lo);
        packed.y = *reinterpret_cast<unsigned*>(&hi);
        Xt[n * 16 + b * 4 + c4] = packed;
    }
    if (g < ND1) cnt1[g] = 0;
    if (g < ND2) cnt2[g] = 0;
}

// Bucketed scatter, both layers, 4 edges per thread (vectorized edge loads,
// 4 independent atomic->store chains in flight). Weight stored as dup half2.
__global__ void fill_kernel(const int4* __restrict__ src1, const int4* __restrict__ dst1,
                            const float4* __restrict__ ew1,
                            const int4* __restrict__ src2, const int4* __restrict__ dst2,
                            const float4* __restrict__ ew2,
                            int* __restrict__ cnt1, int* __restrict__ cnt2,
                            uint2* __restrict__ eb1, uint2* __restrict__ eb2)
{
    const int Q1 = E1 / 4, Q2 = E2 / 4;
    int t = blockIdx.x * blockDim.x + threadIdx.x;

    int4 s4, d4; float4 w4;
    int* cnt; uint2* eb;
    if (t < Q1) {
        s4 = src1[t]; d4 = dst1[t]; w4 = ew1[t];
        cnt = cnt1; eb = eb1;
    } else if (t < Q1 + Q2) {
        int u = t - Q1;
        s4 = src2[u]; d4 = dst2[u]; w4 = ew2[u];
        cnt = cnt2; eb = eb2;
    } else return;

    int sl0 = atomicAdd(&cnt[d4.x], 1);
    int sl1 = atomicAdd(&cnt[d4.y], 1);
    int sl2 = atomicAdd(&cnt[d4.z], 1);
    int sl3 = atomicAdd(&cnt[d4.w], 1);
    if (sl0 < CAP) eb[(size_t)d4.x * CAP + sl0] = make_uint2((unsigned)s4.x, pack_w_half2(w4.x));
    if (sl1 < CAP) eb[(size_t)d4.y * CAP + sl1] = make_uint2((unsigned)s4.y, pack_w_half2(w4.y));
    if (sl2 < CAP) eb[(size_t)d4.z * CAP + sl2] = make_uint2((unsigned)s4.z, pack_w_half2(w4.z));
    if (sl3 < CAP) eb[(size_t)d4.w * CAP + sl3] = make_uint2((unsigned)s4.w, pack_w_half2(w4.w));
}

// Fused aggregate + finalize, TWO warps per dst node (64 threads):
//  - both warps stage the node's <=CAP records into smem (coalesced);
//  - 8 groups of 8 lanes walk every 8th record; each lane gathers one uint4
//    (16B = 8 fp16) of the 128B feature row, HFMA2 fp16 partials
//    (chains ~deg/8 terms; the /deg mean shrinks error before the fp32 GEMM);
//  - intra-warp shfl combine, cross-warp combine via smem, mean, concat
//    [x_res | agg] in smem, mini-GEMM with all 64 threads (1 output each).
// 4 nodes per 256-thread block.
template<bool FINAL>
__global__ void agg_finalize_kernel(const uint4* __restrict__ Xt,    // [Nsrc,8] 16B chunks
                                    const uint2* __restrict__ eb,    // buckets
                                    const int*   __restrict__ cnt,   // [nD]
                                    const int*   __restrict__ res,   // [nD]
                                    const float* __restrict__ W,     // [32,16]
                                    const float* __restrict__ bias,  // [16]
                                    void*        __restrict__ out,
                                    int nD)
{
    __shared__ float sW[512];
    __shared__ float sB[16];
    __shared__ float sh[4][128];     // per node: [0..63]=x_res, [64..127]=mean agg
    __shared__ float spart[4][64];   // cross-warp partials
    __shared__ uint2 srec[4][CAP];

    int t = threadIdx.x;             // 256
    sW[t]       = W[t];
    sW[t + 256] = W[t + 256];
    if (t < 16) sB[t] = bias[t];

    int warp    = t >> 5;
    int lane    = t & 31;
    int slot    = warp >> 1;         // node slot 0..3
    int subwarp = warp & 1;          // which warp of the pair
    int n = blockIdx.x * 4 + slot;
    bool active = (n < nD);

    int deg = 0;
    if (active) {
        deg = cnt[n];
        if (deg > CAP) deg = CAP;
    }
    __syncthreads();                 // weights ready (also orders smem reuse)

    // stage records: 64 threads of the pair, coalesced
    for (int i = subwarp * 32 + lane; i < deg; i += 64)
        srec[slot][i] = eb[(size_t)n * CAP + i];
    __syncthreads();                 // records visible to both warps

    int group = subwarp * 4 + (lane >> 3);   // 0..7 record-parity groups
    int k8    = lane & 7;                    // uint4 index within feature row

    __half2 hacc0 = __float2half2_rn(0.f);
    __half2 hacc1 = hacc0, hacc2 = hacc0, hacc3 = hacc0;
    #pragma unroll 2
    for (int j = group; j < deg; j += 8) {
        uint2 rec = srec[slot][j];
        int     s  = (int)rec.x;
        __half2 wh = *reinterpret_cast<__half2*>(&rec.y);
        uint4 f = Xt[(size_t)s * 8 + k8];            // LDG.128
        const __half2* h = reinterpret_cast<const __half2*>(&f);
        hacc0 = __hfma2(h[0], wh, hacc0);
        hacc1 = __hfma2(h[1], wh, hacc1);
        hacc2 = __hfma2(h[2], wh, hacc2);
        hacc3 = __hfma2(h[3], wh, hacc3);
    }
    // fp16 partials -> fp32; intra-warp combine of this warp's 4 groups
    float acc[8];
    { float2 a;
      a = __half22float2(hacc0); acc[0] = a.x; acc[1] = a.y;
      a = __half22float2(hacc1); acc[2] = a.x; acc[3] = a.y;
      a = __half22float2(hacc2); acc[4] = a.x; acc[5] = a.y;
      a = __half22float2(hacc3); acc[6] = a.x; acc[7] = a.y; }
    #pragma unroll
    for (int q = 0; q < 8; q++) {
        acc[q] += __shfl_down_sync(0xffffffffu, acc[q], 16);
        acc[q] += __shfl_down_sync(0xffffffffu, acc[q], 8);
    }
    // cross-warp: subwarp 1 publishes its partials
    if (subwarp == 1 && lane < 8) {
        #pragma unroll
        for (int q = 0; q < 8; q++)
            spart[slot][lane * 8 + q] = acc[q];
    }
    __syncthreads();
    if (subwarp == 0 && lane < 8 && active) {
        float invd = 1.0f / fmaxf((float)deg, 1.0f);
        #pragma unroll
        for (int q = 0; q < 8; q++)
            sh[slot][64 + 8 * lane + q] = (acc[q] + spart[slot][lane * 8 + q]) * invd;
        int r = res[n];
        uint4 f = Xt[(size_t)r * 8 + lane];
        const __half2* h = reinterpret_cast<const __half2*>(&f);
        #pragma unroll
        for (int q = 0; q < 4; q++) {
            float2 a = __half22float2(h[q]);
            sh[slot][8 * lane + 2 * q]     = a.x;
            sh[slot][8 * lane + 2 * q + 1] = a.y;
        }
    }
    __syncthreads();
    if (!active) return;

    // GEMM: 64 threads per node, one output each (b = idx>>4, o = idx&15)
    int idx = subwarp * 32 + lane;   // 0..63
    int b  = idx >> 4;
    int o  = idx & 15;
    float a0 = sB[o];
    const float* x = &sh[slot][b * 16];
    #pragma unroll
    for (int kk = 0; kk < 16; kk++)
        a0 += x[kk] * sW[kk * 16 + o];
    #pragma unroll
    for (int kk = 0; kk < 16; kk++)
        a0 += x[64 + kk] * sW[(16 + kk) * 16 + o];
    a0 = (a0 > 0.0f) ? a0 : NEG_SLOPE * a0;

    if (FINAL)
        ((float*)out)[((size_t)b * nD + n) * 16 + o] = a0;        // [B,ND,16] fp32
    else
        ((__half*)out)[(size_t)n * BC + idx] = __float2half_rn(a0); // [N,64] fp16
}

// ---------------- launch -----------------------------------------------------

extern "C" void kernel_launch(void* const* d_in, const int* in_sizes, int n_in,
                              void* d_out, int out_size)
{
    const float* X    = (const float*)d_in[0];
    const float* W1   = (const float*)d_in[1];
    const float* b1   = (const float*)d_in[2];
    const float* W2   = (const float*)d_in[3];
    const float* b2   = (const float*)d_in[4];
    const float* ew1  = (const float*)d_in[5];
    const float* ew2  = (const float*)d_in[6];
    const int*   src1 = (const int*)d_in[7];
    const int*   dst1 = (const int*)d_in[8];
    const int*   src2 = (const int*)d_in[9];
    const int*   dst2 = (const int*)d_in[10];
    const int*   res1 = (const int*)d_in[11];
    const int*   res2 = (const int*)d_in[12];
    float* out = (float*)d_out;

    __half *Xt, *h1;
    int *cnt1, *cnt2;
    uint2 *eb1, *eb2;
    cudaGetSymbolAddress((void**)&Xt,   g_Xt);
    cudaGetSymbolAddress((void**)&h1,   g_h1);
    cudaGetSymbolAddress((void**)&cnt1, g_cnt1);
    cudaGetSymbolAddress((void**)&cnt2, g_cnt2);
    cudaGetSymbolAddress((void**)&eb1,  g_eb1);
    cudaGetSymbolAddress((void**)&eb2,  g_eb2);

    // 1. transpose X -> fp16 Xt, zero counters
    prep_kernel<<<(N1 * 16 + 255) / 256, 256>>>((const float4*)X, (uint2*)Xt,
                                                cnt1, cnt2);
    // 2. bucketed edge scatter, both layers (4 edges / thread)
    {
        int nthreads = (E1 + E2) / 4;
        fill_kernel<<<(nthreads + 255) / 256, 256>>>(
            (const int4*)src1, (const int4*)dst1, (const float4*)ew1,
            (const int4*)src2, (const int4*)dst2, (const float4*)ew2,
            cnt1, cnt2, eb1, eb2);
    }
    // 3. layer 1: aggregate + finalize -> h1 (fp16); 2 warps/node
    agg_finalize_kernel<false><<<(ND1 + 3) / 4, 256>>>((const uint4*)Xt, eb1,
                                                       cnt1, res1, W1, b1,
                                                       h1, ND1);
    // 4. layer 2: aggregate + finalize -> d_out [4, ND2, 16] fp32; 2 warps/node
    agg_finalize_kernel<true><<<(ND2 + 3) / 4, 256>>>((const uint4*)h1, eb2,
                                                      cnt2, res2, W2, b2,
                                                      out, ND2);
}

// round 15
// speedup vs baseline: 1.1819x; 1.1819x over previous
#include <cuda_runtime.h>
#include <cuda_fp16.h>
#include <math.h>

// Problem constants (fixed by the reference)
#define N1   100000
#define ND1  50000
#define E1   1600000
#define N2   50000
#define ND2  25000
#define E2   800000
#define BC   64          // B*C = 4*16 values per node
#define NEG_SLOPE 0.01f
#define CAP  96          // per-destination bucket capacity (Poisson(32)+11sigma)

// ---------------- scratch (static device globals; no allocations) -----------
__device__ __half g_Xt [(size_t)N1  * BC];        // fp16 node table, [N,64]
__device__ __half g_h1 [(size_t)ND1 * BC];        // fp16 layer-1 output
__device__ int   g_cnt1[ND1];
__device__ int   g_cnt2[ND2];
__device__ uint2 g_eb1[(size_t)ND1 * CAP];        // (src, w-as-half2) records
__device__ uint2 g_eb2[(size_t)ND2 * CAP];

// ---------------- helpers ----------------------------------------------------

__device__ __forceinline__ unsigned pack_w_half2(float w)
{
    unsigned b = __half_as_ushort(__float2half_rn(w));
    return b | (b << 16);                       // duplicated half2
}

// ---------------- kernels ---------------------------------------------------

// Fused: X[b,n,c] (fp32) -> Xt[n, b*16+c] (fp16)  +  zero degree counters.
__global__ void prep_kernel(const float4* __restrict__ X,
                            uint2* __restrict__ Xt,
                            int*   __restrict__ cnt1,
                            int*   __restrict__ cnt2)
{
    int g = blockIdx.x * blockDim.x + threadIdx.x;   // [0, N1*16)
    if (g < N1 * 16) {
        int n  = g >> 4;
        int b  = (g >> 2) & 3;
        int c4 = g & 3;
        float4 v = X[((size_t)b * N1 + n) * 4 + c4];
        __half2 lo = __floats2half2_rn(v.x, v.y);
        __half2 hi = __floats2half2_rn(v.z, v.w);
        uint2 packed;
        packed.x = *reinterpret_cast<unsigned*>(&lo);
        packed.y = *reinterpret_cast<unsigned*>(&hi);
        Xt[n * 16 + b * 4 + c4] = packed;
    }
    if (g < ND1) cnt1[g] = 0;
    if (g < ND2) cnt2[g] = 0;
}

// Bucketed scatter, both layers, 4 edges per thread (vectorized edge loads,
// 4 independent atomic->store chains in flight). Weight stored as dup half2.
__global__ void fill_kernel(const int4* __restrict__ src1, const int4* __restrict__ dst1,
                            const float4* __restrict__ ew1,
                            const int4* __restrict__ src2, const int4* __restrict__ dst2,
                            const float4* __restrict__ ew2,
                            int* __restrict__ cnt1, int* __restrict__ cnt2,
                            uint2* __restrict__ eb1, uint2* __restrict__ eb2)
{
    const int Q1 = E1 / 4, Q2 = E2 / 4;
    int t = blockIdx.x * blockDim.x + threadIdx.x;

    int4 s4, d4; float4 w4;
    int* cnt; uint2* eb;
    if (t < Q1) {
        s4 = src1[t]; d4 = dst1[t]; w4 = ew1[t];
        cnt = cnt1; eb = eb1;
    } else if (t < Q1 + Q2) {
        int u = t - Q1;
        s4 = src2[u]; d4 = dst2[u]; w4 = ew2[u];
        cnt = cnt2; eb = eb2;
    } else return;

    int sl0 = atomicAdd(&cnt[d4.x], 1);
    int sl1 = atomicAdd(&cnt[d4.y], 1);
    int sl2 = atomicAdd(&cnt[d4.z], 1);
    int sl3 = atomicAdd(&cnt[d4.w], 1);
    if (sl0 < CAP) eb[(size_t)d4.x * CAP + sl0] = make_uint2((unsigned)s4.x, pack_w_half2(w4.x));
    if (sl1 < CAP) eb[(size_t)d4.y * CAP + sl1] = make_uint2((unsigned)s4.y, pack_w_half2(w4.y));
    if (sl2 < CAP) eb[(size_t)d4.z * CAP + sl2] = make_uint2((unsigned)s4.z, pack_w_half2(w4.z));
    if (sl3 < CAP) eb[(size_t)d4.w * CAP + sl3] = make_uint2((unsigned)s4.w, pack_w_half2(w4.w));
}

// Fused aggregate + finalize. One warp per dst node:
//  - warp bulk-stages the node's <=CAP (src, w-half2) records into smem;
//  - 4 groups of 8 lanes walk every 4th record; each lane gathers one uint4
//    (16B = 8 fp16) of the 128B feature row, accumulates with 4 HFMA2
//    (fp16 partials; the /deg mean shrinks their error before the fp32 GEMM);
//    unroll-4 keeps ~4 gathers in flight per thread against L2 latency;
//  - convert to fp32, 2-round shfl combine, mean, concat [x_res | agg] in
//    smem, mini-GEMM [4,32]@[32,16]+b + leaky-ReLU.
// 8 nodes per 256-thread block.
template<bool FINAL>
__global__ void agg_finalize_kernel(const uint4* __restrict__ Xt,    // [Nsrc,8] 16B chunks
                                    const uint2* __restrict__ eb,    // buckets
                                    const int*   __restrict__ cnt,   // [nD]
                                    const int*   __restrict__ res,   // [nD]
                                    const float* __restrict__ W,     // [32,16]
                                    const float* __restrict__ bias,  // [16]
                                    void*        __restrict__ out,
                                    int nD)
{
    __shared__ float sW[512];
    __shared__ float sB[16];
    __shared__ float sh[8][128];     // per node: [0..63]=x_res, [64..127]=mean agg
    __shared__ uint2 srec[8][CAP];

    int t = threadIdx.x;             // 256
    sW[t]       = W[t];
    sW[t + 256] = W[t + 256];
    if (t < 16) sB[t] = bias[t];
    __syncthreads();

    int warp = t >> 5;
    int lane = t & 31;
    int n = blockIdx.x * 8 + warp;
    if (n >= nD) return;

    int deg = cnt[n];
    if (deg > CAP) deg = CAP;

    // stage records (coalesced reads from this node's bucket)
    for (int i = lane; i < deg; i += 32)
        srec[warp][i] = eb[(size_t)n * CAP + i];
    __syncwarp();

    int group = lane >> 3;           // 4 record-parity groups
    int k8    = lane & 7;            // uint4 index within 128B feature row

    __half2 hacc0 = __float2half2_rn(0.f);
    __half2 hacc1 = hacc0, hacc2 = hacc0, hacc3 = hacc0;
    #pragma unroll 4
    for (int j = group; j < deg; j += 4) {
        uint2 rec = srec[warp][j];
        int     s  = (int)rec.x;
        __half2 wh = *reinterpret_cast<__half2*>(&rec.y);
        uint4 f = Xt[(size_t)s * 8 + k8];            // LDG.128
        const __half2* h = reinterpret_cast<const __half2*>(&f);
        hacc0 = __hfma2(h[0], wh, hacc0);
        hacc1 = __hfma2(h[1], wh, hacc1);
        hacc2 = __hfma2(h[2], wh, hacc2);
        hacc3 = __hfma2(h[3], wh, hacc3);
    }
    // convert fp16 partials to fp32, combine the 4 group partials (2 rounds)
    float acc[8];
    { float2 a;
      a = __half22float2(hacc0); acc[0] = a.x; acc[1] = a.y;
      a = __half22float2(hacc1); acc[2] = a.x; acc[3] = a.y;
      a = __half22float2(hacc2); acc[4] = a.x; acc[5] = a.y;
      a = __half22float2(hacc3); acc[6] = a.x; acc[7] = a.y; }
    #pragma unroll
    for (int q = 0; q < 8; q++) {
        acc[q] += __shfl_down_sync(0xffffffffu, acc[q], 16);
        acc[q] += __shfl_down_sync(0xffffffffu, acc[q], 8);
    }

    if (group == 0) {
        float invd = 1.0f / fmaxf((float)deg, 1.0f);
        #pragma unroll
        for (int q = 0; q < 8; q++)
            sh[warp][64 + 8 * k8 + q] = acc[q] * invd;
        int r = res[n];
        uint4 f = Xt[(size_t)r * 8 + k8];
        const __half2* h = reinterpret_cast<const __half2*>(&f);
        #pragma unroll
        for (int q = 0; q < 4; q++) {
            float2 a = __half22float2(h[q]);
            sh[warp][8 * k8 + 2 * q]     = a.x;
            sh[warp][8 * k8 + 2 * q + 1] = a.y;
        }
    }
    __syncwarp();

    // GEMM: each lane computes outputs idx0=2*lane, idx0+1 (same batch row b)
    int idx0 = 2 * lane;
    int b  = idx0 >> 4;
    int o  = idx0 & 15;
    float acc0 = sB[o];
    float acc1 = sB[o + 1];
    const float* x = &sh[warp][b * 16];
    #pragma unroll
    for (int kk = 0; kk < 16; kk++) {
        float xv = x[kk];
        acc0 += xv * sW[kk * 16 + o];
        acc1 += xv * sW[kk * 16 + o + 1];
    }
    #pragma unroll
    for (int kk = 0; kk < 16; kk++) {
        float xv = x[64 + kk];
        acc0 += xv * sW[(16 + kk) * 16 + o];
        acc1 += xv * sW[(16 + kk) * 16 + o + 1];
    }
    acc0 = (acc0 > 0.0f) ? acc0 : NEG_SLOPE * acc0;
    acc1 = (acc1 > 0.0f) ? acc1 : NEG_SLOPE * acc1;

    if (FINAL) {
        float2 v = make_float2(acc0, acc1);
        *reinterpret_cast<float2*>(
            &((float*)out)[((size_t)b * nD + n) * 16 + o]) = v;   // [B,ND,16] fp32
    } else {
        __half2 v = __floats2half2_rn(acc0, acc1);
        *reinterpret_cast<__half2*>(
            &((__half*)out)[(size_t)n * BC + idx0]) = v;          // [N,64] fp16
    }
}

// ---------------- launch -----------------------------------------------------

extern "C" void kernel_launch(void* const* d_in, const int* in_sizes, int n_in,
                              void* d_out, int out_size)
{
    const float* X    = (const float*)d_in[0];
    const float* W1   = (const float*)d_in[1];
    const float* b1   = (const float*)d_in[2];
    const float* W2   = (const float*)d_in[3];
    const float* b2   = (const float*)d_in[4];
    const float* ew1  = (const float*)d_in[5];
    const float* ew2  = (const float*)d_in[6];
    const int*   src1 = (const int*)d_in[7];
    const int*   dst1 = (const int*)d_in[8];
    const int*   src2 = (const int*)d_in[9];
    const int*   dst2 = (const int*)d_in[10];
    const int*   res1 = (const int*)d_in[11];
    const int*   res2 = (const int*)d_in[12];
    float* out = (float*)d_out;

    __half *Xt, *h1;
    int *cnt1, *cnt2;
    uint2 *eb1, *eb2;
    cudaGetSymbolAddress((void**)&Xt,   g_Xt);
    cudaGetSymbolAddress((void**)&h1,   g_h1);
    cudaGetSymbolAddress((void**)&cnt1, g_cnt1);
    cudaGetSymbolAddress((void**)&cnt2, g_cnt2);
    cudaGetSymbolAddress((void**)&eb1,  g_eb1);
    cudaGetSymbolAddress((void**)&eb2,  g_eb2);

    // 1. transpose X -> fp16 Xt, zero counters
    prep_kernel<<<(N1 * 16 + 255) / 256, 256>>>((const float4*)X, (uint2*)Xt,
                                                cnt1, cnt2);
    // 2. bucketed edge scatter, both layers (4 edges / thread)
    {
        int nthreads = (E1 + E2) / 4;
        fill_kernel<<<(nthreads + 255) / 256, 256>>>(
            (const int4*)src1, (const int4*)dst1, (const float4*)ew1,
            (const int4*)src2, (const int4*)dst2, (const float4*)ew2,
            cnt1, cnt2, eb1, eb2);
    }
    // 3. layer 1: aggregate + finalize -> h1 (fp16)
    agg_finalize_kernel<false><<<(ND1 + 7) / 8, 256>>>((const uint4*)Xt, eb1,
                                                       cnt1, res1, W1, b1,
                                                       h1, ND1);
    // 4. layer 2: aggregate + finalize -> d_out [4, ND2, 16] fp32
    agg_finalize_kernel<true><<<(ND2 + 7) / 8, 256>>>((const uint4*)h1, eb2,
                                                      cnt2, res2, W2, b2,
                                                      out, ND2);
}

// round 17
// speedup vs baseline: 1.1979x; 1.0135x over previous
#include <cuda_runtime.h>
#include <cuda_fp16.h>
#include <math.h>

// Problem constants (fixed by the reference)
#define N1   100000
#define ND1  50000
#define E1   1600000
#define N2   50000
#define ND2  25000
#define E2   800000
#define BC   64          // B*C = 4*16 values per node
#define NEG_SLOPE 0.01f
#define CAP  96          // per-destination bucket capacity (Poisson(32)+11sigma)

// ---------------- scratch (static device globals; no allocations) -----------
__device__ __half g_Xt  [(size_t)N1  * BC];       // fp16 node table, [N,64]
__device__ __half g_h1  [(size_t)ND1 * BC];       // fp16 layer-1 output
__device__ __half g_ag1 [(size_t)ND1 * BC];       // fp16 mean-agg, layer 1
__device__ __half g_ag2 [(size_t)ND2 * BC];       // fp16 mean-agg, layer 2
__device__ int   g_cnt1[ND1];
__device__ int   g_cnt2[ND2];
__device__ uint2 g_eb1[(size_t)ND1 * CAP];        // (src, w-as-half2) records
__device__ uint2 g_eb2[(size_t)ND2 * CAP];

// ---------------- helpers ----------------------------------------------------

__device__ __forceinline__ unsigned pack_w_half2(float w)
{
    unsigned b = __half_as_ushort(__float2half_rn(w));
    return b | (b << 16);                       // duplicated half2
}

// ---------------- kernels ---------------------------------------------------

// Fused: X[b,n,c] (fp32) -> Xt[n, b*16+c] (fp16)  +  zero degree counters.
__global__ void prep_kernel(const float4* __restrict__ X,
                            uint2* __restrict__ Xt,
                            int*   __restrict__ cnt1,
                            int*   __restrict__ cnt2)
{
    int g = blockIdx.x * blockDim.x + threadIdx.x;   // [0, N1*16)
    if (g < N1 * 16) {
        int n  = g >> 4;
        int b  = (g >> 2) & 3;
        int c4 = g & 3;
        float4 v = X[((size_t)b * N1 + n) * 4 + c4];
        __half2 lo = __floats2half2_rn(v.x, v.y);
        __half2 hi = __floats2half2_rn(v.z, v.w);
        uint2 packed;
        packed.x = *reinterpret_cast<unsigned*>(&lo);
        packed.y = *reinterpret_cast<unsigned*>(&hi);
        Xt[n * 16 + b * 4 + c4] = packed;
    }
    if (g < ND1) cnt1[g] = 0;
    if (g < ND2) cnt2[g] = 0;
}

// Bucketed scatter, both layers, 4 edges per thread (vectorized edge loads,
// 4 independent atomic->store chains in flight). Weight stored as dup half2.
__global__ void fill_kernel(const int4* __restrict__ src1, const int4* __restrict__ dst1,
                            const float4* __restrict__ ew1,
                            const int4* __restrict__ src2, const int4* __restrict__ dst2,
                            const float4* __restrict__ ew2,
                            int* __restrict__ cnt1, int* __restrict__ cnt2,
                            uint2* __restrict__ eb1, uint2* __restrict__ eb2)
{
    const int Q1 = E1 / 4, Q2 = E2 / 4;
    int t = blockIdx.x * blockDim.x + threadIdx.x;

    int4 s4, d4; float4 w4;
    int* cnt; uint2* eb;
    if (t < Q1) {
        s4 = src1[t]; d4 = dst1[t]; w4 = ew1[t];
        cnt = cnt1; eb = eb1;
    } else if (t < Q1 + Q2) {
        int u = t - Q1;
        s4 = src2[u]; d4 = dst2[u]; w4 = ew2[u];
        cnt = cnt2; eb = eb2;
    } else return;

    int sl0 = atomicAdd(&cnt[d4.x], 1);
    int sl1 = atomicAdd(&cnt[d4.y], 1);
    int sl2 = atomicAdd(&cnt[d4.z], 1);
    int sl3 = atomicAdd(&cnt[d4.w], 1);
    if (sl0 < CAP) eb[(size_t)d4.x * CAP + sl0] = make_uint2((unsigned)s4.x, pack_w_half2(w4.x));
    if (sl1 < CAP) eb[(size_t)d4.y * CAP + sl1] = make_uint2((unsigned)s4.y, pack_w_half2(w4.y));
    if (sl2 < CAP) eb[(size_t)d4.z * CAP + sl2] = make_uint2((unsigned)s4.z, pack_w_half2(w4.z));
    if (sl3 < CAP) eb[(size_t)d4.w * CAP + sl3] = make_uint2((unsigned)s4.w, pack_w_half2(w4.w));
}

// Aggregation ONLY. One warp per dst node:
//  - warp stages the node's <=CAP (src, w-half2) records into smem;
//  - 4 groups of 8 lanes walk every 4th record; each lane gathers one uint4
//    (16B = 8 fp16), HFMA2 fp16 partials (mean /deg shrinks their error);
//  - fp32 shfl combine, mean, group-0 lanes write the 64-half agg vector
//    as one coalesced 128B store per node.
// 8 nodes per 256-thread block.
__global__ void agg_kernel(const uint4* __restrict__ Xt,     // [Nsrc,8] 16B chunks
                           const uint2* __restrict__ eb,     // buckets
                           const int*   __restrict__ cnt,    // [nD]
                           uint4*       __restrict__ aggout, // [nD,8] 16B chunks
                           int nD)
{
    __shared__ uint2 srec[8][CAP];

    int t = threadIdx.x;             // 256
    int warp = t >> 5;
    int lane = t & 31;
    int n = blockIdx.x * 8 + warp;
    if (n >= nD) return;

    int deg = cnt[n];
    if (deg > CAP) deg = CAP;

    for (int i = lane; i < deg; i += 32)
        srec[warp][i] = eb[(size_t)n * CAP + i];
    __syncwarp();

    int group = lane >> 3;           // 4 record-parity groups
    int k8    = lane & 7;            // uint4 index within 128B feature row

    __half2 hacc0 = __float2half2_rn(0.f);
    __half2 hacc1 = hacc0, hacc2 = hacc0, hacc3 = hacc0;
    #pragma unroll 4
    for (int j = group; j < deg; j += 4) {
        uint2 rec = srec[warp][j];
        int     s  = (int)rec.x;
        __half2 wh = *reinterpret_cast<__half2*>(&rec.y);
        uint4 f = Xt[(size_t)s * 8 + k8];            // LDG.128
        const __half2* h = reinterpret_cast<const __half2*>(&f);
        hacc0 = __hfma2(h[0], wh, hacc0);
        hacc1 = __hfma2(h[1], wh, hacc1);
        hacc2 = __hfma2(h[2], wh, hacc2);
        hacc3 = __hfma2(h[3], wh, hacc3);
    }
    float acc[8];
    { float2 a;
      a = __half22float2(hacc0); acc[0] = a.x; acc[1] = a.y;
      a = __half22float2(hacc1); acc[2] = a.x; acc[3] = a.y;
      a = __half22float2(hacc2); acc[4] = a.x; acc[5] = a.y;
      a = __half22float2(hacc3); acc[6] = a.x; acc[7] = a.y; }
    #pragma unroll
    for (int q = 0; q < 8; q++) {
        acc[q] += __shfl_down_sync(0xffffffffu, acc[q], 16);
        acc[q] += __shfl_down_sync(0xffffffffu, acc[q], 8);
    }

    if (group == 0) {
        float invd = 1.0f / fmaxf((float)deg, 1.0f);
        __half2 p0 = __floats2half2_rn(acc[0] * invd, acc[1] * invd);
        __half2 p1 = __floats2half2_rn(acc[2] * invd, acc[3] * invd);
        __half2 p2 = __floats2half2_rn(acc[4] * invd, acc[5] * invd);
        __half2 p3 = __floats2half2_rn(acc[6] * invd, acc[7] * invd);
        uint4 o;
        o.x = *reinterpret_cast<unsigned*>(&p0);
        o.y = *reinterpret_cast<unsigned*>(&p1);
        o.z = *reinterpret_cast<unsigned*>(&p2);
        o.w = *reinterpret_cast<unsigned*>(&p3);
        aggout[(size_t)n * 8 + k8] = o;              // 8 lanes x 16B, coalesced
    }
}

// Dense finalize GEMM. One thread per (n, b): loads its 16 x_res + 16 agg
// values into registers (4x LDG.128), W/bias in smem (broadcast LDS),
// fully unrolled 512-FMA fp32 GEMM, leaky-ReLU, vectorized store.
template<bool FINAL>
__global__ void gemm_kernel(const uint4* __restrict__ Xsrc,   // [Nsrc,8]
                            const uint4* __restrict__ aggb,   // [nD,8]
                            const int*   __restrict__ res,    // [nD]
                            const float* __restrict__ W,      // [32,16]
                            const float* __restrict__ bias,   // [16]
                            void*        __restrict__ out,
                            int nD)
{
    __shared__ float sW[512];
    __shared__ float sB[16];
    int t = threadIdx.x;             // 256
    sW[t]       = W[t];
    sW[t + 256] = W[t + 256];
    if (t < 16) sB[t] = bias[t];
    __syncthreads();

    int idx = blockIdx.x * 256 + t;  // one (n,b) per thread
    if (idx >= nD * 4) return;
    int n = idx >> 2;
    int b = idx & 3;

    int r = res[n];
    uint4 xa = Xsrc[(size_t)r * 8 + b * 2];
    uint4 xb = Xsrc[(size_t)r * 8 + b * 2 + 1];
    uint4 ga = aggb[(size_t)n * 8 + b * 2];
    uint4 gb = aggb[(size_t)n * 8 + b * 2 + 1];

    float x[32];
    {
        const __half2* h;
        h = reinterpret_cast<const __half2*>(&xa);
        #pragma unroll
        for (int q = 0; q < 4; q++) { float2 a = __half22float2(h[q]); x[2*q] = a.x; x[2*q+1] = a.y; }
        h = reinterpret_cast<const __half2*>(&xb);
        #pragma unroll
        for (int q = 0; q < 4; q++) { float2 a = __half22float2(h[q]); x[8+2*q] = a.x; x[8+2*q+1] = a.y; }
        h = reinterpret_cast<const __half2*>(&ga);
        #pragma unroll
        for (int q = 0; q < 4; q++) { float2 a = __half22float2(h[q]); x[16+2*q] = a.x; x[16+2*q+1] = a.y; }
        h = reinterpret_cast<const __half2*>(&gb);
        #pragma unroll
        for (int q = 0; q < 4; q++) { float2 a = __half22float2(h[q]); x[24+2*q] = a.x; x[24+2*q+1] = a.y; }
    }

    float acc[16];
    #pragma unroll
    for (int o = 0; o < 16; o++) acc[o] = sB[o];
    #pragma unroll
    for (int k = 0; k < 32; k++) {
        float xv = x[k];
        #pragma unroll
        for (int o = 0; o < 16; o++)
            acc[o] += xv * sW[k * 16 + o];
    }
    #pragma unroll
    for (int o = 0; o < 16; o++)
        acc[o] = (acc[o] > 0.0f) ? acc[o] : NEG_SLOPE * acc[o];

    if (FINAL) {
        float4* dst = reinterpret_cast<float4*>(
            &((float*)out)[((size_t)b * nD + n) * 16]);
        dst[0] = make_float4(acc[0],  acc[1],  acc[2],  acc[3]);
        dst[1] = make_float4(acc[4],  acc[5],  acc[6],  acc[7]);
        dst[2] = make_float4(acc[8],  acc[9],  acc[10], acc[11]);
        dst[3] = make_float4(acc[12], acc[13], acc[14], acc[15]);
    } else {
        uint4 o0, o1;
        __half2 p;
        p = __floats2half2_rn(acc[0],  acc[1]);  o0.x = *reinterpret_cast<unsigned*>(&p);
        p = __floats2half2_rn(acc[2],  acc[3]);  o0.y = *reinterpret_cast<unsigned*>(&p);
        p = __floats2half2_rn(acc[4],  acc[5]);  o0.z = *reinterpret_cast<unsigned*>(&p);
        p = __floats2half2_rn(acc[6],  acc[7]);  o0.w = *reinterpret_cast<unsigned*>(&p);
        p = __floats2half2_rn(acc[8],  acc[9]);  o1.x = *reinterpret_cast<unsigned*>(&p);
        p = __floats2half2_rn(acc[10], acc[11]); o1.y = *reinterpret_cast<unsigned*>(&p);
        p = __floats2half2_rn(acc[12], acc[13]); o1.z = *reinterpret_cast<unsigned*>(&p);
        p = __floats2half2_rn(acc[14], acc[15]); o1.w = *reinterpret_cast<unsigned*>(&p);
        uint4* dst = reinterpret_cast<uint4*>(&((__half*)out)[(size_t)n * BC + b * 16]);
        dst[0] = o0;
        dst[1] = o1;
    }
}

// ---------------- launch -----------------------------------------------------

extern "C" void kernel_launch(void* const* d_in, const int* in_sizes, int n_in,
                              void* d_out, int out_size)
{
    const float* X    = (const float*)d_in[0];
    const float* W1   = (const float*)d_in[1];
    const float* b1   = (const float*)d_in[2];
    const float* W2   = (const float*)d_in[3];
    const float* b2   = (const float*)d_in[4];
    const float* ew1  = (const float*)d_in[5];
    const float* ew2  = (const float*)d_in[6];
    const int*   src1 = (const int*)d_in[7];
    const int*   dst1 = (const int*)d_in[8];
    const int*   src2 = (const int*)d_in[9];
    const int*   dst2 = (const int*)d_in[10];
    const int*   res1 = (const int*)d_in[11];
    const int*   res2 = (const int*)d_in[12];
    float* out = (float*)d_out;

    __half *Xt, *h1, *ag1, *ag2;
    int *cnt1, *cnt2;
    uint2 *eb1, *eb2;
    cudaGetSymbolAddress((void**)&Xt,   g_Xt);
    cudaGetSymbolAddress((void**)&h1,   g_h1);
    cudaGetSymbolAddress((void**)&ag1,  g_ag1);
    cudaGetSymbolAddress((void**)&ag2,  g_ag2);
    cudaGetSymbolAddress((void**)&cnt1, g_cnt1);
    cudaGetSymbolAddress((void**)&cnt2, g_cnt2);
    cudaGetSymbolAddress((void**)&eb1,  g_eb1);
    cudaGetSymbolAddress((void**)&eb2,  g_eb2);

    // 1. transpose X -> fp16 Xt, zero counters
    prep_kernel<<<(N1 * 16 + 255) / 256, 256>>>((const float4*)X, (uint2*)Xt,
                                                cnt1, cnt2);
    // 2. bucketed edge scatter, both layers (4 edges / thread)
    {
        int nthreads = (E1 + E2) / 4;
        fill_kernel<<<(nthreads + 255) / 256, 256>>>(
            (const int4*)src1, (const int4*)dst1, (const float4*)ew1,
            (const int4*)src2, (const int4*)dst2, (const float4*)ew2,
            cnt1, cnt2, eb1, eb2);
    }
    // 3. layer 1: aggregate -> ag1; finalize GEMM -> h1 (fp16)
    agg_kernel<<<(ND1 + 7) / 8, 256>>>((const uint4*)Xt, eb1, cnt1,
                                       (uint4*)ag1, ND1);
    gemm_kernel<false><<<(ND1 * 4 + 255) / 256, 256>>>(
        (const uint4*)Xt, (const uint4*)ag1, res1, W1, b1, h1, ND1);
    // 4. layer 2: aggregate -> ag2; finalize GEMM -> d_out [4, ND2, 16] fp32
    agg_kernel<<<(ND2 + 7) / 8, 256>>>((const uint4*)h1, eb2, cnt2,
                                       (uint4*)ag2, ND2);
    gemm_kernel<true><<<(ND2 * 4 + 255) / 256, 256>>>(
        (const uint4*)h1, (const uint4*)ag2, res2, W2, b2, out, ND2);
}